// round 15
// baseline (speedup 1.0000x reference)
#include <cuda_runtime.h>
#include <cuda_bf16.h>
#include <cstdint>

// Problem constants (VOCAB=32000, D_MODEL=512, BATCH=8, SEQ=4096)
constexpr int B_ = 8;
constexpr int S_ = 4096;
constexpr int D_ = 512;
constexpr int SPB = 4;                  // s-values per block (64 threads each)

// pe[s,d] = sin(angle) for even d, cos(angle) for odd d,
// angle = s / 10000^(2d/512)  (per-index exponent, faithful to reference)
__device__ __forceinline__ float pe_val(float sf, int d) {
    const float C       = -0.05190512648261504f;  // -2/512 * log2(10000)
    const float INV2PI  =  0.15915494309189535f;
    const float PI2_HI  =  6.2831855f;            // fl32(2*pi)
    const float PI2_LO  = -1.7484556e-7f;         // 2*pi - PI2_HI
    const float PIO2    =  1.5707963267948966f;

    float w   = exp2f((float)d * C);              // 10000^(-2d/512)
    float off = (d & 1) ? PIO2 : 0.0f;            // odd d -> cos = sin(x + pi/2)
    float ang = fmaf(sf, w, off);
    float k   = rintf(ang * INV2PI);
    float r   = fmaf(k, -PI2_HI, ang);
    r         = fmaf(k, -PI2_LO, r);
    return __sinf(r);                             // |r| <= pi -> accurate
}

struct F8 { float v[8]; };

// 256-bit gather (LDG.E.256): 32 lanes x 32B = 8 full 128B lines / instruction.
__device__ __forceinline__ F8 ldg256(const float* p) {
    F8 r;
    asm volatile("ld.global.nc.v8.b32 {%0,%1,%2,%3,%4,%5,%6,%7}, [%8];"
                 : "=f"(r.v[0]), "=f"(r.v[1]), "=f"(r.v[2]), "=f"(r.v[3]),
                   "=f"(r.v[4]), "=f"(r.v[5]), "=f"(r.v[6]), "=f"(r.v[7])
                 : "l"(p));
    return r;
}

// 256-bit store (STG.E.256).
__device__ __forceinline__ void stg256(float* p, const F8& r) {
    asm volatile("st.global.v8.b32 [%0], {%1,%2,%3,%4,%5,%6,%7,%8};"
                 :: "l"(p),
                    "f"(r.v[0]), "f"(r.v[1]), "f"(r.v[2]), "f"(r.v[3]),
                    "f"(r.v[4]), "f"(r.v[5]), "f"(r.v[6]), "f"(r.v[7])
                 : "memory");
}

__global__ __launch_bounds__(256) void emb_pe_kernel(
    const int*   __restrict__ tokens,   // [B, S]
    const float* __restrict__ table,    // [V, D]
    float*       __restrict__ out)      // [B, S, D]
{
    // 64 threads per s: thread owns 8 consecutive floats (32B) of the row.
    const int sIdx = threadIdx.x >> 6;            // 0..3
    const int t    = threadIdx.x & 63;            // 0..63
    const int s    = blockIdx.x * SPB + sIdx;
    const int d0   = t * 8;

    // Uniform token loads (broadcast within each warp; no smem, no barrier).
    int tok[B_];
    #pragma unroll
    for (int b = 0; b < B_; b++)
        tok[b] = __ldg(tokens + b * S_ + s);

    // PE for the 8 owned columns (batch-invariant; computed once, reused 8x).
    const float sf = (float)s;
    float pe[8];
    #pragma unroll
    for (int i = 0; i < 8; i++)
        pe[i] = pe_val(sf, d0 + i);

    // Two passes of 4 batch rows: 4 LDG.256 in flight per pass (128B/thread),
    // half the L1tex instruction count of the LDG.128 variants.
    #pragma unroll
    for (int pass = 0; pass < 2; pass++) {
        const int bb = pass * 4;
        F8 r[4];
        #pragma unroll
        for (int b = 0; b < 4; b++)
            r[b] = ldg256(table + (size_t)tok[bb + b] * D_ + d0);

        #pragma unroll
        for (int b = 0; b < 4; b++) {
            #pragma unroll
            for (int i = 0; i < 8; i++)
                r[b].v[i] += pe[i];
            stg256(out + ((size_t)(bb + b) * S_ + s) * D_ + d0, r[b]);
        }
    }
}

extern "C" void kernel_launch(void* const* d_in, const int* in_sizes, int n_in,
                              void* d_out, int out_size) {
    const int*   tokens = (const int*)d_in[0];     // [8, 4096] int32
    const float* table  = (const float*)d_in[1];   // [32000, 512] float32
    float*       out    = (float*)d_out;           // [8, 4096, 512] float32
    (void)in_sizes; (void)n_in; (void)out_size;

    emb_pe_kernel<<<S_ / SPB, 256>>>(tokens, table, out);
}